// round 8
// baseline (speedup 1.0000x reference)
#include <cuda_runtime.h>
#include <mma.h>

using namespace nvcuda;

constexpr int NU = 16000;
constexpr int NM = 8000;
constexpr int E  = 64;
constexpr int L  = 3;

// Layer output buffers (layers 1..3); layer 0 = input embeddings read directly.
__device__ float g_us[L * NU * E];
__device__ float g_ms[L * NM * E];

constexpr int LDA = 20;   // As pitch (16 + 4), multiple of 4 for wmma ld
constexpr int LDB = 68;   // Bs pitch (64 + 4)
constexpr int LDT = 68;   // Ts pitch
constexpr int LDW = 65;   // Ws pitch (conflict-free epilogue reads)

__global__ __launch_bounds__(128)
void gemm_layer_kernel(const float* __restrict__ uadj,
                       const float* __restrict__ madj,
                       const float* __restrict__ uemb,
                       const float* __restrict__ memb,
                       const float* __restrict__ Wu,
                       const float* __restrict__ bu,
                       const float* __restrict__ Wm,
                       const float* __restrict__ bm,
                       int layer)
{
    __shared__ float As[64 * LDA];
    __shared__ float Bs[16 * LDB];
    __shared__ float Ts[64 * LDT];
    __shared__ float Ws[64 * LDW];

    const float* prevU = (layer == 0) ? uemb : (g_us + (layer - 1) * NU * E);
    const float* prevM = (layer == 0) ? memb : (g_ms + (layer - 1) * NM * E);

    const int bid = blockIdx.x;
    const float *adj, *bop, *self, *W, *bias;
    float* outp;
    int m0, K;
    if (bid < NM / 64) {                 // movie side first (K = 16000, longest blocks)
        m0 = bid * 64; K = NU;
        adj = madj; bop = prevU; self = prevM;
        W = Wm + layer * E * E; bias = bm + layer * E;
        outp = g_ms + layer * NM * E;
    } else {                              // user side (K = 8000)
        m0 = (bid - NM / 64) * 64; K = NM;
        adj = uadj; bop = prevM; self = prevU;
        W = Wu + layer * E * E; bias = bu + layer * E;
        outp = g_us + layer * NU * E;
    }

    const int t    = threadIdx.x;
    const int wid  = t >> 5;
    const int wr   = wid >> 1;            // 2x2 warp grid over the 64x64 tile
    const int wc   = wid & 1;

    // Stage W (64x64) into smem once; only read after later __syncthreads.
    for (int s = t; s < E * E; s += 128)
        Ws[(s >> 6) * LDW + (s & 63)] = W[s];

    wmma::fragment<wmma::accumulator, 16, 16, 8, float> acc[2][2];
    #pragma unroll
    for (int i = 0; i < 2; i++)
        #pragma unroll
        for (int j = 0; j < 2; j++)
            wmma::fill_fragment(acc[i][j], 0.0f);

    const float* adjBase = adj + (long long)m0 * K;

    for (int k0 = 0; k0 < K; k0 += 16) {
        // A tile: 64 x 16 (adjacency), read exactly once from DRAM
        #pragma unroll
        for (int rep = 0; rep < 2; rep++) {
            int s  = t + rep * 128;                 // 256 float4 slots
            int r  = s >> 2;
            int c4 = (s & 3) << 2;
            float4 v = *(const float4*)(adjBase + (long long)r * K + k0 + c4);
            *(float4*)(As + r * LDA + c4) = v;
        }
        // B tile: 16 x 64 (prev embeddings, L2-resident)
        #pragma unroll
        for (int rep = 0; rep < 2; rep++) {
            int s  = t + rep * 128;
            int r  = s >> 4;
            int c4 = (s & 15) << 2;
            float4 v = *(const float4*)(bop + (k0 + r) * E + c4);
            *(float4*)(Bs + r * LDB + c4) = v;
        }
        __syncthreads();

        #pragma unroll
        for (int kk = 0; kk < 16; kk += 8) {
            wmma::fragment<wmma::matrix_a, 16, 16, 8, wmma::precision::tf32, wmma::row_major> a[2];
            wmma::fragment<wmma::matrix_b, 16, 16, 8, wmma::precision::tf32, wmma::row_major> b[2];
            #pragma unroll
            for (int i = 0; i < 2; i++) {
                wmma::load_matrix_sync(a[i], As + (wr * 32 + 16 * i) * LDA + kk, LDA);
                #pragma unroll
                for (int x = 0; x < a[i].num_elements; x++)
                    a[i].x[x] = wmma::__float_to_tf32(a[i].x[x]);
            }
            #pragma unroll
            for (int j = 0; j < 2; j++) {
                wmma::load_matrix_sync(b[j], Bs + kk * LDB + wc * 32 + 16 * j, LDB);
                #pragma unroll
                for (int x = 0; x < b[j].num_elements; x++)
                    b[j].x[x] = wmma::__float_to_tf32(b[j].x[x]);
            }
            #pragma unroll
            for (int i = 0; i < 2; i++)
                #pragma unroll
                for (int j = 0; j < 2; j++)
                    wmma::mma_sync(acc[i][j], a[i], b[j], acc[i][j]);
        }
        __syncthreads();
    }

    // T = adj @ emb_prev  ->  smem
    #pragma unroll
    for (int i = 0; i < 2; i++)
        #pragma unroll
        for (int j = 0; j < 2; j++)
            wmma::store_matrix_sync(Ts + (wr * 32 + 16 * i) * LDT + (wc * 32 + 16 * j),
                                    acc[i][j], LDT, wmma::mem_row_major);
    __syncthreads();

    // T += self_prev
    for (int s = t; s < 64 * 64; s += 128) {
        int r = s >> 6, c = s & 63;
        Ts[r * LDT + c] += self[(m0 + r) * E + c];
    }
    __syncthreads();

    // Y = leaky_relu(T @ W^T + 2b)   (exact fp32, small: 64x64x64 per CTA)
    for (int s = t; s < 64 * 64; s += 128) {
        int r = s >> 6, c = s & 63;
        const float* trow = Ts + r * LDT;     // broadcast across lanes sharing r
        const float* wrow = Ws + c * LDW;     // pitch 65 -> conflict-free
        float sum = 2.0f * bias[c];
        #pragma unroll
        for (int k = 0; k < 64; k++)
            sum = fmaf(trow[k], wrow[k], sum);
        outp[(m0 + r) * E + c] = (sum >= 0.0f) ? sum : 0.01f * sum;
    }
}

// One warp per output element: gather 4 layer-rows of u and m, elementwise
// multiply, dot with Wo, warp-reduce.
__global__ __launch_bounds__(256)
void gather_kernel(const float* __restrict__ uemb, const float* __restrict__ memb,
                   const float* __restrict__ Wo, const float* __restrict__ bo,
                   const int* __restrict__ uid, const int* __restrict__ mid,
                   float* __restrict__ out, int B)
{
    int gw   = (int)((blockIdx.x * blockDim.x + threadIdx.x) >> 5);
    int lane = threadIdx.x & 31;
    if (gw >= B) return;

    const int u = uid[gw];
    const int m = mid[gw];

    float acc = 0.0f;
    {
        const float* ur = uemb + u * E;
        const float* mr = memb + m * E;
        #pragma unroll
        for (int rep = 0; rep < 2; rep++) {
            int e = lane + rep * 32;
            acc = fmaf(ur[e] * mr[e], Wo[e], acc);
        }
    }
    #pragma unroll
    for (int l = 0; l < L; l++) {
        const float* ul = g_us + l * NU * E + u * E;
        const float* ml = g_ms + l * NM * E + m * E;
        const float* w  = Wo + (l + 1) * E;
        #pragma unroll
        for (int rep = 0; rep < 2; rep++) {
            int e = lane + rep * 32;
            acc = fmaf(ul[e] * ml[e], w[e], acc);
        }
    }
    #pragma unroll
    for (int o = 16; o > 0; o >>= 1)
        acc += __shfl_down_sync(0xffffffffu, acc, o);
    if (lane == 0) out[gw] = acc + bo[0];
}

extern "C" void kernel_launch(void* const* d_in, const int* in_sizes, int n_in,
                              void* d_out, int out_size)
{
    const float* uadj = (const float*)d_in[0];
    const float* madj = (const float*)d_in[1];
    const float* uemb = (const float*)d_in[2];
    const float* memb = (const float*)d_in[3];
    const float* Wu   = (const float*)d_in[4];
    const float* bu   = (const float*)d_in[5];
    const float* Wm   = (const float*)d_in[6];
    const float* bm   = (const float*)d_in[7];
    const float* Wo   = (const float*)d_in[8];
    const float* bo   = (const float*)d_in[9];
    const int*   uid  = (const int*)d_in[10];
    const int*   mid  = (const int*)d_in[11];
    float* out = (float*)d_out;

    const int B = in_sizes[10];

    const int grid = NM / 64 + NU / 64;   // 125 movie + 250 user = 375 CTAs
    for (int l = 0; l < L; l++)
        gemm_layer_kernel<<<grid, 128>>>(uadj, madj, uemb, memb, Wu, bu, Wm, bm, l);

    const int gblocks = (B + 7) / 8;      // 8 warps (outputs) per 256-thread block
    gather_kernel<<<gblocks, 256>>>(uemb, memb, Wo, bo, uid, mid, out, B);
}

// round 9
// speedup vs baseline: 1.4156x; 1.4156x over previous
#include <cuda_runtime.h>
#include <mma.h>

using namespace nvcuda;

constexpr int NU = 16000;
constexpr int NM = 8000;
constexpr int E  = 64;
constexpr int L  = 3;

// Layer output buffers (layers 1..3); layer 0 = input embeddings read directly.
__device__ float g_us[L * NU * E];
__device__ float g_ms[L * NM * E];

constexpr int BK     = 32;
constexpr int STAGES = 4;
constexpr int LDA2   = BK + 4;        // 36 floats (144 B, 16B-aligned rows)
constexpr int LDB2   = 68;            // 272 B rows
constexpr int A_STAGE = 64 * LDA2;    // floats per A stage
constexpr int B_STAGE = BK * LDB2;    // floats per B stage
constexpr int SMEM_BYTES = STAGES * (A_STAGE + B_STAGE) * 4;   // 71680 B

constexpr int LDT = 68;
constexpr int LDW = 65;

__device__ __forceinline__ unsigned sptr(const void* p) {
    return (unsigned)__cvta_generic_to_shared(p);
}
#define CP16(dst, src) asm volatile("cp.async.cg.shared.global [%0], [%1], 16;\n" :: "r"(dst), "l"(src))
#define CP_COMMIT()    asm volatile("cp.async.commit_group;\n")
#define CP_WAIT(n)     asm volatile("cp.async.wait_group %0;\n" :: "n"(n))

__global__ __launch_bounds__(128)
void gemm_layer_kernel(const float* __restrict__ uadj,
                       const float* __restrict__ madj,
                       const float* __restrict__ uemb,
                       const float* __restrict__ memb,
                       const float* __restrict__ Wu,
                       const float* __restrict__ bu,
                       const float* __restrict__ Wm,
                       const float* __restrict__ bm,
                       int layer)
{
    extern __shared__ float smem[];
    float* As = smem;                            // [STAGES][A_STAGE]
    float* Bs = smem + STAGES * A_STAGE;         // [STAGES][B_STAGE]
    // Epilogue buffers alias the pipeline region (only used after mainloop):
    float* Ts = smem;                            // 64*LDT floats
    float* Ws = smem + 64 * LDT;                 // 64*LDW floats

    const float* prevU = (layer == 0) ? uemb : (g_us + (layer - 1) * NU * E);
    const float* prevM = (layer == 0) ? memb : (g_ms + (layer - 1) * NM * E);

    const int bid = blockIdx.x;
    const float *adj, *bop, *self, *W, *bias;
    float* outp;
    int m0, K;
    if (bid < NM / 64) {                 // movie side first (K = 16000, longest blocks)
        m0 = bid * 64; K = NU;
        adj = madj; bop = prevU; self = prevM;
        W = Wm + layer * E * E; bias = bm + layer * E;
        outp = g_ms + layer * NM * E;
    } else {                              // user side (K = 8000)
        m0 = (bid - NM / 64) * 64; K = NM;
        adj = uadj; bop = prevM; self = prevU;
        W = Wu + layer * E * E; bias = bu + layer * E;
        outp = g_us + layer * NU * E;
    }

    const int t   = threadIdx.x;
    const int wid = t >> 5;
    const int wr  = wid >> 1;            // 2x2 warp grid over the 64x64 tile
    const int wc  = wid & 1;

    const float* adjBase = adj + (long long)m0 * K;

    // Per-thread load coordinates (4 float4 slots each for A and B per stage)
    int rA[4], cA[4], rB[4], cB[4];
    #pragma unroll
    for (int rep = 0; rep < 4; rep++) {
        int s = t + rep * 128;
        rA[rep] = s >> 3;  cA[rep] = (s & 7)  << 2;   // A: 64 rows x 32 cols
        rB[rep] = s >> 4;  cB[rep] = (s & 15) << 2;   // B: 32 rows x 64 cols
    }

    auto load_stage = [&](int stage, int k0) {
        float* a_s = As + stage * A_STAGE;
        float* b_s = Bs + stage * B_STAGE;
        #pragma unroll
        for (int rep = 0; rep < 4; rep++)
            CP16(sptr(a_s + rA[rep] * LDA2 + cA[rep]),
                 adjBase + rA[rep] * K + k0 + cA[rep]);
        #pragma unroll
        for (int rep = 0; rep < 4; rep++)
            CP16(sptr(b_s + rB[rep] * LDB2 + cB[rep]),
                 bop + (k0 + rB[rep]) * E + cB[rep]);
    };

    wmma::fragment<wmma::accumulator, 16, 16, 8, float> acc[2][2];
    #pragma unroll
    for (int i = 0; i < 2; i++)
        #pragma unroll
        for (int j = 0; j < 2; j++)
            wmma::fill_fragment(acc[i][j], 0.0f);

    const int num_k = K / BK;

    // Prefetch STAGES-1 stages
    #pragma unroll
    for (int st = 0; st < STAGES - 1; st++) {
        load_stage(st, st * BK);
        CP_COMMIT();
    }

    for (int k = 0; k < num_k; k++) {
        CP_WAIT(STAGES - 2);             // stage k ready
        __syncthreads();                 // also: everyone finished reading stage k-1

        int kn = k + STAGES - 1;         // next stage to fill = (k-1) % STAGES slot
        if (kn < num_k) load_stage(kn % STAGES, kn * BK);
        CP_COMMIT();

        const float* a_s = As + (k % STAGES) * A_STAGE;
        const float* b_s = Bs + (k % STAGES) * B_STAGE;

        #pragma unroll
        for (int kk = 0; kk < BK; kk += 8) {
            wmma::fragment<wmma::matrix_a, 16, 16, 8, wmma::precision::tf32, wmma::row_major> a[2];
            wmma::fragment<wmma::matrix_b, 16, 16, 8, wmma::precision::tf32, wmma::row_major> b[2];
            #pragma unroll
            for (int i = 0; i < 2; i++) {
                wmma::load_matrix_sync(a[i], a_s + (wr * 32 + 16 * i) * LDA2 + kk, LDA2);
                #pragma unroll
                for (int x = 0; x < a[i].num_elements; x++)
                    a[i].x[x] = wmma::__float_to_tf32(a[i].x[x]);
            }
            #pragma unroll
            for (int j = 0; j < 2; j++) {
                wmma::load_matrix_sync(b[j], b_s + kk * LDB2 + wc * 32 + 16 * j, LDB2);
                #pragma unroll
                for (int x = 0; x < b[j].num_elements; x++)
                    b[j].x[x] = wmma::__float_to_tf32(b[j].x[x]);
            }
            #pragma unroll
            for (int i = 0; i < 2; i++)
                #pragma unroll
                for (int j = 0; j < 2; j++)
                    wmma::mma_sync(acc[i][j], a[i], b[j], acc[i][j]);
        }
    }

    __syncthreads();   // all warps done with pipeline smem; safe to alias

    // T = adj @ emb_prev -> smem ; stage W into smem
    #pragma unroll
    for (int i = 0; i < 2; i++)
        #pragma unroll
        for (int j = 0; j < 2; j++)
            wmma::store_matrix_sync(Ts + (wr * 32 + 16 * i) * LDT + (wc * 32 + 16 * j),
                                    acc[i][j], LDT, wmma::mem_row_major);
    for (int s = t; s < E * E; s += 128)
        Ws[(s >> 6) * LDW + (s & 63)] = W[s];
    __syncthreads();

    // T += self_prev
    for (int s = t; s < 64 * 64; s += 128) {
        int r = s >> 6, c = s & 63;
        Ts[r * LDT + c] += self[(m0 + r) * E + c];
    }
    __syncthreads();

    // Y = leaky_relu(T @ W^T + 2b)   (exact fp32, 64x64x64 per CTA)
    for (int s = t; s < 64 * 64; s += 128) {
        int r = s >> 6, c = s & 63;
        const float* trow = Ts + r * LDT;
        const float* wrow = Ws + c * LDW;
        float sum = 2.0f * bias[c];
        #pragma unroll
        for (int k = 0; k < 64; k++)
            sum = fmaf(trow[k], wrow[k], sum);
        outp[(m0 + r) * E + c] = (sum >= 0.0f) ? sum : 0.01f * sum;
    }
}

// One warp per output element: gather 4 layer-rows of u and m, elementwise
// multiply, dot with Wo, warp-reduce.
__global__ __launch_bounds__(256)
void gather_kernel(const float* __restrict__ uemb, const float* __restrict__ memb,
                   const float* __restrict__ Wo, const float* __restrict__ bo,
                   const int* __restrict__ uid, const int* __restrict__ mid,
                   float* __restrict__ out, int B)
{
    int gw   = (int)((blockIdx.x * blockDim.x + threadIdx.x) >> 5);
    int lane = threadIdx.x & 31;
    if (gw >= B) return;

    const int u = uid[gw];
    const int m = mid[gw];

    float acc = 0.0f;
    {
        const float* ur = uemb + u * E;
        const float* mr = memb + m * E;
        #pragma unroll
        for (int rep = 0; rep < 2; rep++) {
            int e = lane + rep * 32;
            acc = fmaf(ur[e] * mr[e], Wo[e], acc);
        }
    }
    #pragma unroll
    for (int l = 0; l < L; l++) {
        const float* ul = g_us + l * NU * E + u * E;
        const float* ml = g_ms + l * NM * E + m * E;
        const float* w  = Wo + (l + 1) * E;
        #pragma unroll
        for (int rep = 0; rep < 2; rep++) {
            int e = lane + rep * 32;
            acc = fmaf(ul[e] * ml[e], w[e], acc);
        }
    }
    #pragma unroll
    for (int o = 16; o > 0; o >>= 1)
        acc += __shfl_down_sync(0xffffffffu, acc, o);
    if (lane == 0) out[gw] = acc + bo[0];
}

extern "C" void kernel_launch(void* const* d_in, const int* in_sizes, int n_in,
                              void* d_out, int out_size)
{
    const float* uadj = (const float*)d_in[0];
    const float* madj = (const float*)d_in[1];
    const float* uemb = (const float*)d_in[2];
    const float* memb = (const float*)d_in[3];
    const float* Wu   = (const float*)d_in[4];
    const float* bu   = (const float*)d_in[5];
    const float* Wm   = (const float*)d_in[6];
    const float* bm   = (const float*)d_in[7];
    const float* Wo   = (const float*)d_in[8];
    const float* bo   = (const float*)d_in[9];
    const int*   uid  = (const int*)d_in[10];
    const int*   mid  = (const int*)d_in[11];
    float* out = (float*)d_out;

    const int B = in_sizes[10];

    cudaFuncSetAttribute(gemm_layer_kernel,
                         cudaFuncAttributeMaxDynamicSharedMemorySize, SMEM_BYTES);

    const int grid = NM / 64 + NU / 64;   // 125 movie + 250 user = 375 CTAs
    for (int l = 0; l < L; l++)
        gemm_layer_kernel<<<grid, 128, SMEM_BYTES>>>(uadj, madj, uemb, memb,
                                                     Wu, bu, Wm, bm, l);

    const int gblocks = (B + 7) / 8;      // 8 warps (outputs) per 256-thread block
    gather_kernel<<<gblocks, 256>>>(uemb, memb, Wo, bo, uid, mid, out, B);
}

// round 10
// speedup vs baseline: 1.4190x; 1.0024x over previous
#include <cuda_runtime.h>
#include <mma.h>

using namespace nvcuda;

constexpr int NU = 16000;
constexpr int NM = 8000;
constexpr int E  = 64;
constexpr int L  = 3;

// Layer output buffers (layers 1..3); layer 0 = input embeddings read directly.
__device__ float g_us[L * NU * E];
__device__ float g_ms[L * NM * E];

constexpr int BK     = 32;
constexpr int STAGES = 4;
constexpr int LDA2   = BK + 4;        // 36 floats (144 B, 16B-aligned rows)
constexpr int LDB2   = 68;            // 272 B rows
constexpr int A_STAGE = 64 * LDA2;    // floats per A stage
constexpr int B_STAGE = BK * LDB2;    // floats per B stage
constexpr int SMEM_BYTES = STAGES * (A_STAGE + B_STAGE) * 4;   // 71680 B

constexpr int LDT = 68;
constexpr int LDW = 65;

__device__ __forceinline__ unsigned sptr(const void* p) {
    return (unsigned)__cvta_generic_to_shared(p);
}
#define CP16(dst, src) asm volatile("cp.async.cg.shared.global [%0], [%1], 16;\n" :: "r"(dst), "l"(src))
#define CP_COMMIT()    asm volatile("cp.async.commit_group;\n")
#define CP_WAIT(n)     asm volatile("cp.async.wait_group %0;\n" :: "n"(n))

__global__ __launch_bounds__(128)
void gemm_layer_kernel(const float* __restrict__ uadj,
                       const float* __restrict__ madj,
                       const float* __restrict__ uemb,
                       const float* __restrict__ memb,
                       const float* __restrict__ Wu,
                       const float* __restrict__ bu,
                       const float* __restrict__ Wm,
                       const float* __restrict__ bm,
                       int layer)
{
    extern __shared__ float smem[];
    float* As = smem;                            // [STAGES][A_STAGE]
    float* Bs = smem + STAGES * A_STAGE;         // [STAGES][B_STAGE]
    // Epilogue buffers alias the pipeline region (only used after mainloop):
    float* Ts = smem;                            // 64*LDT floats
    float* Ws = smem + 64 * LDT;                 // 64*LDW floats

    const float* prevU = (layer == 0) ? uemb : (g_us + (layer - 1) * NU * E);
    const float* prevM = (layer == 0) ? memb : (g_ms + (layer - 1) * NM * E);

    const int bid = blockIdx.x;
    const float *adj, *bop, *self, *W, *bias;
    float* outp;
    int m0, K;
    if (bid < NM / 64) {                 // movie side first (K = 16000, longest blocks)
        m0 = bid * 64; K = NU;
        adj = madj; bop = prevU; self = prevM;
        W = Wm + layer * E * E; bias = bm + layer * E;
        outp = g_ms + layer * NM * E;
    } else {                              // user side (K = 8000)
        m0 = (bid - NM / 64) * 64; K = NM;
        adj = uadj; bop = prevM; self = prevU;
        W = Wu + layer * E * E; bias = bu + layer * E;
        outp = g_us + layer * NU * E;
    }

    const int t   = threadIdx.x;
    const int wid = t >> 5;
    const int wr  = wid >> 1;            // 2x2 warp grid over the 64x64 tile
    const int wc  = wid & 1;

    const float* adjBase = adj + (long long)m0 * K;

    // Per-thread load coordinates (4 float4 slots each for A and B per stage)
    int rA[4], cA[4], rB[4], cB[4];
    #pragma unroll
    for (int rep = 0; rep < 4; rep++) {
        int s = t + rep * 128;
        rA[rep] = s >> 3;  cA[rep] = (s & 7)  << 2;   // A: 64 rows x 32 cols
        rB[rep] = s >> 4;  cB[rep] = (s & 15) << 2;   // B: 32 rows x 64 cols
    }

    auto load_stage = [&](int stage, int k0) {
        float* a_s = As + stage * A_STAGE;
        float* b_s = Bs + stage * B_STAGE;
        #pragma unroll
        for (int rep = 0; rep < 4; rep++)
            CP16(sptr(a_s + rA[rep] * LDA2 + cA[rep]),
                 adjBase + rA[rep] * K + k0 + cA[rep]);
        #pragma unroll
        for (int rep = 0; rep < 4; rep++)
            CP16(sptr(b_s + rB[rep] * LDB2 + cB[rep]),
                 bop + (k0 + rB[rep]) * E + cB[rep]);
    };

    wmma::fragment<wmma::accumulator, 16, 16, 8, float> acc[2][2];
    #pragma unroll
    for (int i = 0; i < 2; i++)
        #pragma unroll
        for (int j = 0; j < 2; j++)
            wmma::fill_fragment(acc[i][j], 0.0f);

    const int num_k = K / BK;

    // Prefetch STAGES-1 stages
    #pragma unroll
    for (int st = 0; st < STAGES - 1; st++) {
        load_stage(st, st * BK);
        CP_COMMIT();
    }

    for (int k = 0; k < num_k; k++) {
        CP_WAIT(STAGES - 2);             // stage k ready
        __syncthreads();                 // also: everyone finished reading stage k-1

        int kn = k + STAGES - 1;         // next stage to fill = (k-1) % STAGES slot
        if (kn < num_k) load_stage(kn % STAGES, kn * BK);
        CP_COMMIT();

        const float* a_s = As + (k % STAGES) * A_STAGE;
        const float* b_s = Bs + (k % STAGES) * B_STAGE;

        #pragma unroll
        for (int kk = 0; kk < BK; kk += 8) {
            wmma::fragment<wmma::matrix_a, 16, 16, 8, wmma::precision::tf32, wmma::row_major> a[2];
            wmma::fragment<wmma::matrix_b, 16, 16, 8, wmma::precision::tf32, wmma::row_major> b[2];
            #pragma unroll
            for (int i = 0; i < 2; i++) {
                wmma::load_matrix_sync(a[i], a_s + (wr * 32 + 16 * i) * LDA2 + kk, LDA2);
                #pragma unroll
                for (int x = 0; x < a[i].num_elements; x++)
                    a[i].x[x] = wmma::__float_to_tf32(a[i].x[x]);
            }
            #pragma unroll
            for (int j = 0; j < 2; j++) {
                wmma::load_matrix_sync(b[j], b_s + kk * LDB2 + wc * 32 + 16 * j, LDB2);
                #pragma unroll
                for (int x = 0; x < b[j].num_elements; x++)
                    b[j].x[x] = wmma::__float_to_tf32(b[j].x[x]);
            }
            #pragma unroll
            for (int i = 0; i < 2; i++)
                #pragma unroll
                for (int j = 0; j < 2; j++)
                    wmma::mma_sync(acc[i][j], a[i], b[j], acc[i][j]);
        }
    }

    __syncthreads();   // all warps done with pipeline smem; safe to alias

    // T = adj @ emb_prev -> smem ; stage W into smem
    #pragma unroll
    for (int i = 0; i < 2; i++)
        #pragma unroll
        for (int j = 0; j < 2; j++)
            wmma::store_matrix_sync(Ts + (wr * 32 + 16 * i) * LDT + (wc * 32 + 16 * j),
                                    acc[i][j], LDT, wmma::mem_row_major);
    for (int s = t; s < E * E; s += 128)
        Ws[(s >> 6) * LDW + (s & 63)] = W[s];
    __syncthreads();

    // T += self_prev
    for (int s = t; s < 64 * 64; s += 128) {
        int r = s >> 6, c = s & 63;
        Ts[r * LDT + c] += self[(m0 + r) * E + c];
    }
    __syncthreads();

    // Y = leaky_relu(T @ W^T + 2b)   (exact fp32, 64x64x64 per CTA)
    for (int s = t; s < 64 * 64; s += 128) {
        int r = s >> 6, c = s & 63;
        const float* trow = Ts + r * LDT;
        const float* wrow = Ws + c * LDW;
        float sum = 2.0f * bias[c];
        #pragma unroll
        for (int k = 0; k < 64; k++)
            sum = fmaf(trow[k], wrow[k], sum);
        outp[(m0 + r) * E + c] = (sum >= 0.0f) ? sum : 0.01f * sum;
    }
}

// One warp per output element: gather 4 layer-rows of u and m, elementwise
// multiply, dot with Wo, warp-reduce.
__global__ __launch_bounds__(256)
void gather_kernel(const float* __restrict__ uemb, const float* __restrict__ memb,
                   const float* __restrict__ Wo, const float* __restrict__ bo,
                   const int* __restrict__ uid, const int* __restrict__ mid,
                   float* __restrict__ out, int B)
{
    int gw   = (int)((blockIdx.x * blockDim.x + threadIdx.x) >> 5);
    int lane = threadIdx.x & 31;
    if (gw >= B) return;

    const int u = uid[gw];
    const int m = mid[gw];

    float acc = 0.0f;
    {
        const float* ur = uemb + u * E;
        const float* mr = memb + m * E;
        #pragma unroll
        for (int rep = 0; rep < 2; rep++) {
            int e = lane + rep * 32;
            acc = fmaf(ur[e] * mr[e], Wo[e], acc);
        }
    }
    #pragma unroll
    for (int l = 0; l < L; l++) {
        const float* ul = g_us + l * NU * E + u * E;
        const float* ml = g_ms + l * NM * E + m * E;
        const float* w  = Wo + (l + 1) * E;
        #pragma unroll
        for (int rep = 0; rep < 2; rep++) {
            int e = lane + rep * 32;
            acc = fmaf(ul[e] * ml[e], w[e], acc);
        }
    }
    #pragma unroll
    for (int o = 16; o > 0; o >>= 1)
        acc += __shfl_down_sync(0xffffffffu, acc, o);
    if (lane == 0) out[gw] = acc + bo[0];
}

extern "C" void kernel_launch(void* const* d_in, const int* in_sizes, int n_in,
                              void* d_out, int out_size)
{
    const float* uadj = (const float*)d_in[0];
    const float* madj = (const float*)d_in[1];
    const float* uemb = (const float*)d_in[2];
    const float* memb = (const float*)d_in[3];
    const float* Wu   = (const float*)d_in[4];
    const float* bu   = (const float*)d_in[5];
    const float* Wm   = (const float*)d_in[6];
    const float* bm   = (const float*)d_in[7];
    const float* Wo   = (const float*)d_in[8];
    const float* bo   = (const float*)d_in[9];
    const int*   uid  = (const int*)d_in[10];
    const int*   mid  = (const int*)d_in[11];
    float* out = (float*)d_out;

    const int B = in_sizes[10];

    cudaFuncSetAttribute(gemm_layer_kernel,
                         cudaFuncAttributeMaxDynamicSharedMemorySize, SMEM_BYTES);

    const int grid = NM / 64 + NU / 64;   // 125 movie + 250 user = 375 CTAs
    for (int l = 0; l < L; l++)
        gemm_layer_kernel<<<grid, 128, SMEM_BYTES>>>(uadj, madj, uemb, memb,
                                                     Wu, bu, Wm, bm, l);

    const int gblocks = (B + 7) / 8;      // 8 warps (outputs) per 256-thread block
    gather_kernel<<<gblocks, 256>>>(uemb, memb, Wo, bo, uid, mid, out, B);
}

// round 12
// speedup vs baseline: 4.5073x; 3.1764x over previous
#include <cuda_runtime.h>
#include <cuda_fp16.h>
#include <mma.h>
#include <cstdint>

using namespace nvcuda;

constexpr int NU = 16000;
constexpr int NM = 8000;
constexpr int E  = 64;
constexpr int L  = 3;

// fp16 copies of the adjacency matrices (converted once per run)
__device__ __half g_uadjh[(size_t)NU * NM];
__device__ __half g_madjh[(size_t)NM * NU];
// fp16 input embeddings (layer-0 B operands)
__device__ __half g_uh0[NU * E];
__device__ __half g_mh0[NM * E];
// fp32 layer outputs (self-term of next layer + gather)
__device__ float g_us[L * NU * E];
__device__ float g_ms[L * NM * E];
// fp16 layer outputs (next layer's B operand)
__device__ __half g_ush[L * NU * E];
__device__ __half g_msh[L * NM * E];
// split-K partial accumulators
constexpr int SPLIT_M = 4;   // movie side: K=16000 -> 4 x 4000
constexpr int SPLIT_U = 2;   // user  side: K= 8000 -> 2 x 4000
__device__ float g_pm[SPLIT_M * NM * E];
__device__ float g_pu[SPLIT_U * NU * E];

// ------------------- cp.async helpers -------------------
__device__ __forceinline__ unsigned sptr(const void* p) {
    return (unsigned)__cvta_generic_to_shared(p);
}
#define CP16(dst, src) asm volatile("cp.async.cg.shared.global [%0], [%1], 16;\n" :: "r"(dst), "l"(src))
#define CP_COMMIT()    asm volatile("cp.async.commit_group;\n")
#define CP_WAIT(n)     asm volatile("cp.async.wait_group %0;\n" :: "n"(n))

// ------------------- tiling -------------------
constexpr int BK      = 32;           // k-chunk (halves)
constexpr int STAGES  = 4;
constexpr int LDA_H   = 40;           // A smem pitch in halves (80 B rows)
constexpr int LDB_H   = 80;           // B smem pitch in halves (160 B rows)
constexpr int A_STAGE_H = 64 * LDA_H; // 2560 halves = 5120 B
constexpr int B_STAGE_H = BK * LDB_H; // 2560 halves = 5120 B
constexpr int SMEM_BYTES = STAGES * (A_STAGE_H + B_STAGE_H) * 2;  // 40960 B

constexpr int NITER   = 125;          // 4000 / BK, identical for every CTA
constexpr int GRID_G  = 125 * SPLIT_M + 250 * SPLIT_U;  // 500 + 500 = 1000

__global__ __launch_bounds__(128)
void gemm_half_kernel(int layer)
{
    extern __shared__ __half sh[];
    __half* As = sh;                               // [STAGES][A_STAGE_H]
    __half* Bs = sh + STAGES * A_STAGE_H;          // [STAGES][B_STAGE_H]

    const int bid = blockIdx.x;
    const __half *adj, *bh;
    float* part;
    int tile, K;
    if (bid < 125 * SPLIT_M) {                     // movie side
        tile = bid >> 2;
        const int split = bid & 3;
        K = NU;
        adj  = g_madjh;
        bh   = (layer == 0) ? g_uh0 : (g_ush + (layer - 1) * NU * E);
        part = g_pm + (size_t)split * NM * E;
        adj += (size_t)0;                          // base fixed below
        bh  += (size_t)(split * 4000) * E;
        adj += (size_t)tile * 64 * K + split * 4000;
    } else {                                        // user side
        const int u = bid - 125 * SPLIT_M;
        tile = u >> 1;
        const int split = u & 1;
        K = NM;
        adj  = g_uadjh;
        bh   = (layer == 0) ? g_mh0 : (g_msh + (layer - 1) * NM * E);
        part = g_pu + (size_t)split * NU * E;
        bh  += (size_t)(split * 4000) * E;
        adj += (size_t)tile * 64 * K + split * 4000;
    }
    const int m0 = tile * 64;

    const int t   = threadIdx.x;
    const int wid = t >> 5;
    const int wr  = wid >> 1;                      // 2x2 warp grid over 64x64
    const int wc  = wid & 1;

    // per-thread cp.async slots
    // A: 64 rows x 32 halves = 256 x (8 halves); B: 32 rows x 64 halves = 256 x (8 halves)
    auto load_stage = [&](int st, int k0) {
        __half* a_s = As + st * A_STAGE_H;
        __half* b_s = Bs + st * B_STAGE_H;
        #pragma unroll
        for (int rep = 0; rep < 2; rep++) {
            int id = t + rep * 128;
            int r = id >> 2, c = id & 3;           // A row, 16B chunk
            CP16(sptr(a_s + r * LDA_H + c * 8), adj + (size_t)r * K + k0 + c * 8);
        }
        #pragma unroll
        for (int rep = 0; rep < 2; rep++) {
            int id = t + rep * 128;
            int r = id >> 3, c = id & 7;           // B row (k), 16B chunk
            CP16(sptr(b_s + r * LDB_H + c * 8), bh + (size_t)(k0 + r) * E + c * 8);
        }
    };

    wmma::fragment<wmma::accumulator, 16, 16, 16, float> acc[2][2];
    #pragma unroll
    for (int i = 0; i < 2; i++)
        #pragma unroll
        for (int j = 0; j < 2; j++)
            wmma::fill_fragment(acc[i][j], 0.0f);

    #pragma unroll
    for (int st = 0; st < STAGES - 1; st++) { load_stage(st, st * BK); CP_COMMIT(); }

    for (int k = 0; k < NITER; k++) {
        CP_WAIT(STAGES - 2);                       // stage k resident
        __syncthreads();                           // everyone done reading stage k-1

        const int kn = k + STAGES - 1;
        if (kn < NITER) load_stage(kn & 3, kn * BK);
        CP_COMMIT();

        const __half* a_s = As + (k & 3) * A_STAGE_H;
        const __half* b_s = Bs + (k & 3) * B_STAGE_H;

        #pragma unroll
        for (int kk = 0; kk < BK; kk += 16) {
            wmma::fragment<wmma::matrix_a, 16, 16, 16, __half, wmma::row_major> a[2];
            wmma::fragment<wmma::matrix_b, 16, 16, 16, __half, wmma::row_major> b[2];
            #pragma unroll
            for (int i = 0; i < 2; i++)
                wmma::load_matrix_sync(a[i], a_s + (wr * 32 + 16 * i) * LDA_H + kk, LDA_H);
            #pragma unroll
            for (int j = 0; j < 2; j++)
                wmma::load_matrix_sync(b[j], b_s + kk * LDB_H + wc * 32 + 16 * j, LDB_H);
            #pragma unroll
            for (int i = 0; i < 2; i++)
                #pragma unroll
                for (int j = 0; j < 2; j++)
                    wmma::mma_sync(acc[i][j], a[i], b[j], acc[i][j]);
        }
    }

    // dump 64x64 fp32 partial tile straight to gmem
    #pragma unroll
    for (int i = 0; i < 2; i++)
        #pragma unroll
        for (int j = 0; j < 2; j++)
            wmma::store_matrix_sync(part + (size_t)(m0 + wr * 32 + 16 * i) * E
                                         + (wc * 32 + 16 * j),
                                    acc[i][j], E, wmma::mem_row_major);
}

// ------------- reduce partials + fused epilogue -------------
// blocks 0..62: movie rows (63*128 >= 8000); blocks 63..187: user rows.
__global__ __launch_bounds__(128)
void reduce_epilogue_kernel(const float* __restrict__ uemb,
                            const float* __restrict__ memb,
                            const float* __restrict__ Wu,
                            const float* __restrict__ bu,
                            const float* __restrict__ Wm,
                            const float* __restrict__ bm,
                            int layer)
{
    __shared__ float Ws[64 * 65];
    const int bid = blockIdx.x;
    const int t   = threadIdx.x;

    int row0, Mtot, S;
    const float *part, *self, *W, *bias;
    float* outp; __half* outh;
    if (bid < 63) {                                   // movie
        row0 = bid * 128; Mtot = NM; S = SPLIT_M;
        part = g_pm;
        self = (layer == 0) ? memb : (g_ms + (layer - 1) * NM * E);
        W = Wm + layer * E * E; bias = bm + layer * E;
        outp = g_ms + layer * NM * E;  outh = g_msh + layer * NM * E;
    } else {                                          // user
        row0 = (bid - 63) * 128; Mtot = NU; S = SPLIT_U;
        part = g_pu;
        self = (layer == 0) ? uemb : (g_us + (layer - 1) * NU * E);
        W = Wu + layer * E * E; bias = bu + layer * E;
        outp = g_us + layer * NU * E;  outh = g_ush + layer * NU * E;
    }

    for (int s = t; s < E * E; s += 128)
        Ws[(s >> 6) * 65 + (s & 63)] = W[s];
    __syncthreads();

    const int r = row0 + t;
    if (r >= Mtot) return;

    float tv[64];
    {
        const float4* sp = (const float4*)(self + (size_t)r * E);
        #pragma unroll
        for (int i = 0; i < 16; i++) {
            float4 v = sp[i];
            tv[4 * i + 0] = v.x; tv[4 * i + 1] = v.y;
            tv[4 * i + 2] = v.z; tv[4 * i + 3] = v.w;
        }
    }
    for (int s = 0; s < S; s++) {
        const float4* pp = (const float4*)(part + (size_t)s * Mtot * E + (size_t)r * E);
        #pragma unroll
        for (int i = 0; i < 16; i++) {
            float4 v = pp[i];
            tv[4 * i + 0] += v.x; tv[4 * i + 1] += v.y;
            tv[4 * i + 2] += v.z; tv[4 * i + 3] += v.w;
        }
    }

    for (int c0 = 0; c0 < 64; c0 += 4) {
        float a0 = 2.0f * bias[c0 + 0];
        float a1 = 2.0f * bias[c0 + 1];
        float a2 = 2.0f * bias[c0 + 2];
        float a3 = 2.0f * bias[c0 + 3];
        const float* w0 = Ws + (c0 + 0) * 65;
        const float* w1 = Ws + (c0 + 1) * 65;
        const float* w2 = Ws + (c0 + 2) * 65;
        const float* w3 = Ws + (c0 + 3) * 65;
        #pragma unroll
        for (int k = 0; k < 64; k++) {
            float tk = tv[k];
            a0 = fmaf(tk, w0[k], a0);
            a1 = fmaf(tk, w1[k], a1);
            a2 = fmaf(tk, w2[k], a2);
            a3 = fmaf(tk, w3[k], a3);
        }
        a0 = (a0 >= 0.0f) ? a0 : 0.01f * a0;
        a1 = (a1 >= 0.0f) ? a1 : 0.01f * a1;
        a2 = (a2 >= 0.0f) ? a2 : 0.01f * a2;
        a3 = (a3 >= 0.0f) ? a3 : 0.01f * a3;
        *(float4*)(outp + (size_t)r * E + c0) = make_float4(a0, a1, a2, a3);
        __half2 h0 = __float22half2_rn(make_float2(a0, a1));
        __half2 h1 = __float22half2_rn(make_float2(a2, a3));
        uint2 o;
        o.x = *(unsigned*)&h0; o.y = *(unsigned*)&h1;
        *(uint2*)(outh + (size_t)r * E + c0) = o;
    }
}

// ------------- fp32 -> fp16 bulk convert (8 elems/thread) -------------
__global__ __launch_bounds__(256)
void f2h_kernel(const float* __restrict__ src, __half* __restrict__ dst, long long n8)
{
    long long i = (long long)blockIdx.x * blockDim.x + threadIdx.x;
    if (i >= n8) return;
    const float4* s = (const float4*)src;
    float4 a = s[2 * i], b = s[2 * i + 1];
    __half2 h0 = __float22half2_rn(make_float2(a.x, a.y));
    __half2 h1 = __float22half2_rn(make_float2(a.z, a.w));
    __half2 h2 = __float22half2_rn(make_float2(b.x, b.y));
    __half2 h3 = __float22half2_rn(make_float2(b.z, b.w));
    uint4 o;
    o.x = *(unsigned*)&h0; o.y = *(unsigned*)&h1;
    o.z = *(unsigned*)&h2; o.w = *(unsigned*)&h3;
    ((uint4*)dst)[i] = o;
}

// ------------- gather: one warp per output element -------------
__global__ __launch_bounds__(256)
void gather_kernel(const float* __restrict__ uemb, const float* __restrict__ memb,
                   const float* __restrict__ Wo, const float* __restrict__ bo,
                   const int* __restrict__ uid, const int* __restrict__ mid,
                   float* __restrict__ out, int B)
{
    int gw   = (int)((blockIdx.x * blockDim.x + threadIdx.x) >> 5);
    int lane = threadIdx.x & 31;
    if (gw >= B) return;

    const int u = uid[gw];
    const int m = mid[gw];

    float acc = 0.0f;
    {
        const float* ur = uemb + u * E;
        const float* mr = memb + m * E;
        #pragma unroll
        for (int rep = 0; rep < 2; rep++) {
            int e = lane + rep * 32;
            acc = fmaf(ur[e] * mr[e], Wo[e], acc);
        }
    }
    #pragma unroll
    for (int l = 0; l < L; l++) {
        const float* ul = g_us + l * NU * E + u * E;
        const float* ml = g_ms + l * NM * E + m * E;
        const float* w  = Wo + (l + 1) * E;
        #pragma unroll
        for (int rep = 0; rep < 2; rep++) {
            int e = lane + rep * 32;
            acc = fmaf(ul[e] * ml[e], w[e], acc);
        }
    }
    #pragma unroll
    for (int o = 16; o > 0; o >>= 1)
        acc += __shfl_down_sync(0xffffffffu, acc, o);
    if (lane == 0) out[gw] = acc + bo[0];
}

extern "C" void kernel_launch(void* const* d_in, const int* in_sizes, int n_in,
                              void* d_out, int out_size)
{
    const float* uadj = (const float*)d_in[0];
    const float* madj = (const float*)d_in[1];
    const float* uemb = (const float*)d_in[2];
    const float* memb = (const float*)d_in[3];
    const float* Wu   = (const float*)d_in[4];
    const float* bu   = (const float*)d_in[5];
    const float* Wm   = (const float*)d_in[6];
    const float* bm   = (const float*)d_in[7];
    const float* Wo   = (const float*)d_in[8];
    const float* bo   = (const float*)d_in[9];
    const int*   uid  = (const int*)d_in[10];
    const int*   mid  = (const int*)d_in[11];
    float* out = (float*)d_out;

    const int B = in_sizes[10];

    cudaFuncSetAttribute(gemm_half_kernel,
                         cudaFuncAttributeMaxDynamicSharedMemorySize, SMEM_BYTES);

    // fp16 conversions (device symbols referenced inside kernels; get raw ptrs)
    __half *uadjh, *madjh, *uh0, *mh0;
    cudaGetSymbolAddress((void**)&uadjh, g_uadjh);
    cudaGetSymbolAddress((void**)&madjh, g_madjh);
    cudaGetSymbolAddress((void**)&uh0,   g_uh0);
    cudaGetSymbolAddress((void**)&mh0,   g_mh0);

    const long long nadj8 = (long long)NU * NM / 8;
    f2h_kernel<<<(unsigned)((nadj8 + 255) / 256), 256>>>(uadj, uadjh, nadj8);
    f2h_kernel<<<(unsigned)((nadj8 + 255) / 256), 256>>>(madj, madjh, nadj8);
    const long long nue8 = (long long)NU * E / 8;
    const long long nme8 = (long long)NM * E / 8;
    f2h_kernel<<<(unsigned)((nue8 + 255) / 256), 256>>>(uemb, uh0, nue8);
    f2h_kernel<<<(unsigned)((nme8 + 255) / 256), 256>>>(memb, mh0, nme8);

    for (int l = 0; l < L; l++) {
        gemm_half_kernel<<<GRID_G, 128, SMEM_BYTES>>>(l);
        reduce_epilogue_kernel<<<63 + 125, 128>>>(uemb, memb, Wu, bu, Wm, bm, l);
    }

    const int gblocks = (B + 7) / 8;
    gather_kernel<<<gblocks, 256>>>(uemb, memb, Wo, bo, uid, mid, out, B);
}

// round 15
// speedup vs baseline: 4.5641x; 1.0126x over previous
#include <cuda_runtime.h>
#include <cuda_fp16.h>
#include <mma.h>
#include <cstdint>

using namespace nvcuda;

constexpr int NU = 16000;
constexpr int NM = 8000;
constexpr int E  = 64;
constexpr int L  = 3;

// fp16 copies of the adjacency matrices (converted once per run)
__device__ __half g_uadjh[(size_t)NU * NM];
__device__ __half g_madjh[(size_t)NM * NU];
// fp16 input embeddings (layer-0 B operands)
__device__ __half g_uh0[NU * E];
__device__ __half g_mh0[NM * E];
// fp32 layer outputs (self-term of next layer + gather)
__device__ float g_us[L * NU * E];
__device__ float g_ms[L * NM * E];
// fp16 layer outputs (next layer's B operand)
__device__ __half g_ush[L * NU * E];
__device__ __half g_msh[L * NM * E];
// split-K partial accumulators
constexpr int SPLIT_M = 4;   // movie side: K=16000 -> 4 x 4000
constexpr int SPLIT_U = 2;   // user  side: K= 8000 -> 2 x 4000
__device__ float g_pm[SPLIT_M * NM * E];
__device__ float g_pu[SPLIT_U * NU * E];

// ------------------- cp.async helpers -------------------
__device__ __forceinline__ unsigned sptr(const void* p) {
    return (unsigned)__cvta_generic_to_shared(p);
}
#define CP16(dst, src) asm volatile("cp.async.cg.shared.global [%0], [%1], 16;\n" :: "r"(dst), "l"(src))
#define CP_COMMIT()    asm volatile("cp.async.commit_group;\n")
#define CP_WAIT(n)     asm volatile("cp.async.wait_group %0;\n" :: "n"(n))

// ------------------- tiling -------------------
constexpr int BK      = 32;           // k-chunk (halves)
constexpr int STAGES  = 3;
constexpr int LDA_H   = 40;           // A pitch: 80 B = 20 banks -> conflict-free LDSM
constexpr int LDB_H   = 72;           // B pitch: 144 B = 36 banks (≡4 mod 32) -> conflict-free LDSM
constexpr int A_STAGE_H = 64 * LDA_H; // 2560 halves
constexpr int B_STAGE_H = BK * LDB_H; // 2304 halves
constexpr int SMEM_BYTES = STAGES * (A_STAGE_H + B_STAGE_H) * 2;  // 29184 B -> 7 CTAs/SM

constexpr int NITER   = 125;          // 4000 / BK, identical for every CTA
constexpr int GRID_G  = 125 * SPLIT_M + 250 * SPLIT_U;  // 500 + 500 = 1000

__global__ __launch_bounds__(128)
void gemm_half_kernel(int layer)
{
    extern __shared__ __half sh[];
    __half* As = sh;                               // [STAGES][A_STAGE_H]
    __half* Bs = sh + STAGES * A_STAGE_H;          // [STAGES][B_STAGE_H]

    const int bid = blockIdx.x;
    const __half *adj, *bh;
    float* part;
    int tile, K;
    if (bid < 125 * SPLIT_M) {                     // movie side
        tile = bid >> 2;
        const int split = bid & 3;
        K = NU;
        adj  = g_madjh;
        bh   = (layer == 0) ? g_uh0 : (g_ush + (layer - 1) * NU * E);
        part = g_pm + (size_t)split * NM * E;
        bh  += (size_t)(split * 4000) * E;
        adj += (size_t)tile * 64 * K + split * 4000;
    } else {                                        // user side
        const int u = bid - 125 * SPLIT_M;
        tile = u >> 1;
        const int split = u & 1;
        K = NM;
        adj  = g_uadjh;
        bh   = (layer == 0) ? g_mh0 : (g_msh + (layer - 1) * NM * E);
        part = g_pu + (size_t)split * NU * E;
        bh  += (size_t)(split * 4000) * E;
        adj += (size_t)tile * 64 * K + split * 4000;
    }
    const int m0 = tile * 64;

    const int t   = threadIdx.x;
    const int wid = t >> 5;
    const int wr  = wid >> 1;                      // 2x2 warp grid over 64x64
    const int wc  = wid & 1;

    // per-thread cp.async slots
    // A: 64 rows x 32 halves = 256 x (8 halves); B: 32 rows x 64 halves = 256 x (8 halves)
    auto load_stage = [&](int st, int k0) {
        __half* a_s = As + st * A_STAGE_H;
        __half* b_s = Bs + st * B_STAGE_H;
        #pragma unroll
        for (int rep = 0; rep < 2; rep++) {
            int id = t + rep * 128;
            int r = id >> 2, c = id & 3;           // A row, 16B chunk
            CP16(sptr(a_s + r * LDA_H + c * 8), adj + (size_t)r * K + k0 + c * 8);
        }
        #pragma unroll
        for (int rep = 0; rep < 2; rep++) {
            int id = t + rep * 128;
            int r = id >> 3, c = id & 7;           // B row (k), 16B chunk
            CP16(sptr(b_s + r * LDB_H + c * 8), bh + (size_t)(k0 + r) * E + c * 8);
        }
    };

    wmma::fragment<wmma::accumulator, 16, 16, 16, float> acc[2][2];
    #pragma unroll
    for (int i = 0; i < 2; i++)
        #pragma unroll
        for (int j = 0; j < 2; j++)
            wmma::fill_fragment(acc[i][j], 0.0f);

    #pragma unroll
    for (int st = 0; st < STAGES - 1; st++) { load_stage(st, st * BK); CP_COMMIT(); }

    int stc = 0, stn = STAGES - 1;                 // consume / next-fill stage slots
    for (int k = 0; k < NITER; k++) {
        CP_WAIT(STAGES - 2);                       // stage k resident
        __syncthreads();                           // everyone done reading stage k-1

        const int kn = k + STAGES - 1;
        if (kn < NITER) load_stage(stn, kn * BK);
        CP_COMMIT();
        if (++stn == STAGES) stn = 0;

        const __half* a_s = As + stc * A_STAGE_H;
        const __half* b_s = Bs + stc * B_STAGE_H;
        if (++stc == STAGES) stc = 0;

        #pragma unroll
        for (int kk = 0; kk < BK; kk += 16) {
            wmma::fragment<wmma::matrix_a, 16, 16, 16, __half, wmma::row_major> a[2];
            wmma::fragment<wmma::matrix_b, 16, 16, 16, __half, wmma::row_major> b[2];
            #pragma unroll
            for (int i = 0; i < 2; i++)
                wmma::load_matrix_sync(a[i], a_s + (wr * 32 + 16 * i) * LDA_H + kk, LDA_H);
            #pragma unroll
            for (int j = 0; j < 2; j++)
                wmma::load_matrix_sync(b[j], b_s + kk * LDB_H + wc * 32 + 16 * j, LDB_H);
            #pragma unroll
            for (int i = 0; i < 2; i++)
                #pragma unroll
                for (int j = 0; j < 2; j++)
                    wmma::mma_sync(acc[i][j], a[i], b[j], acc[i][j]);
        }
    }

    // dump 64x64 fp32 partial tile straight to gmem
    #pragma unroll
    for (int i = 0; i < 2; i++)
        #pragma unroll
        for (int j = 0; j < 2; j++)
            wmma::store_matrix_sync(part + (size_t)(m0 + wr * 32 + 16 * i) * E
                                         + (wc * 32 + 16 * j),
                                    acc[i][j], E, wmma::mem_row_major);
}

// ------------- reduce partials + fused epilogue -------------
// blocks 0..62: movie rows (63*128 >= 8000); blocks 63..187: user rows.
__global__ __launch_bounds__(128)
void reduce_epilogue_kernel(const float* __restrict__ uemb,
                            const float* __restrict__ memb,
                            const float* __restrict__ Wu,
                            const float* __restrict__ bu,
                            const float* __restrict__ Wm,
                            const float* __restrict__ bm,
                            int layer)
{
    __shared__ float Ws[64 * 65];
    const int bid = blockIdx.x;
    const int t   = threadIdx.x;

    int row0, Mtot, S;
    const float *part, *self, *W, *bias;
    float* outp; __half* outh;
    if (bid < 63) {                                   // movie
        row0 = bid * 128; Mtot = NM; S = SPLIT_M;
        part = g_pm;
        self = (layer == 0) ? memb : (g_ms + (layer - 1) * NM * E);
        W = Wm + layer * E * E; bias = bm + layer * E;
        outp = g_ms + layer * NM * E;  outh = g_msh + layer * NM * E;
    } else {                                          // user
        row0 = (bid - 63) * 128; Mtot = NU; S = SPLIT_U;
        part = g_pu;
        self = (layer == 0) ? uemb : (g_us + (layer - 1) * NU * E);
        W = Wu + layer * E * E; bias = bu + layer * E;
        outp = g_us + layer * NU * E;  outh = g_ush + layer * NU * E;
    }

    for (int s = t; s < E * E; s += 128)
        Ws[(s >> 6) * 65 + (s & 63)] = W[s];
    __syncthreads();

    const int r = row0 + t;
    if (r >= Mtot) return;

    float tv[64];
    {
        const float4* sp = (const float4*)(self + (size_t)r * E);
        #pragma unroll
        for (int i = 0; i < 16; i++) {
            float4 v = sp[i];
            tv[4 * i + 0] = v.x; tv[4 * i + 1] = v.y;
            tv[4 * i + 2] = v.z; tv[4 * i + 3] = v.w;
        }
    }
    for (int s = 0; s < S; s++) {
        const float4* pp = (const float4*)(part + (size_t)s * Mtot * E + (size_t)r * E);
        #pragma unroll
        for (int i = 0; i < 16; i++) {
            float4 v = pp[i];
            tv[4 * i + 0] += v.x; tv[4 * i + 1] += v.y;
            tv[4 * i + 2] += v.z; tv[4 * i + 3] += v.w;
        }
    }

    for (int c0 = 0; c0 < 64; c0 += 4) {
        float a0 = 2.0f * bias[c0 + 0];
        float a1 = 2.0f * bias[c0 + 1];
        float a2 = 2.0f * bias[c0 + 2];
        float a3 = 2.0f * bias[c0 + 3];
        const float* w0 = Ws + (c0 + 0) * 65;
        const float* w1 = Ws + (c0 + 1) * 65;
        const float* w2 = Ws + (c0 + 2) * 65;
        const float* w3 = Ws + (c0 + 3) * 65;
        #pragma unroll
        for (int k = 0; k < 64; k++) {
            float tk = tv[k];
            a0 = fmaf(tk, w0[k], a0);
            a1 = fmaf(tk, w1[k], a1);
            a2 = fmaf(tk, w2[k], a2);
            a3 = fmaf(tk, w3[k], a3);
        }
        a0 = (a0 >= 0.0f) ? a0 : 0.01f * a0;
        a1 = (a1 >= 0.0f) ? a1 : 0.01f * a1;
        a2 = (a2 >= 0.0f) ? a2 : 0.01f * a2;
        a3 = (a3 >= 0.0f) ? a3 : 0.01f * a3;
        *(float4*)(outp + (size_t)r * E + c0) = make_float4(a0, a1, a2, a3);
        __half2 h0 = __float22half2_rn(make_float2(a0, a1));
        __half2 h1 = __float22half2_rn(make_float2(a2, a3));
        uint2 o;
        o.x = *(unsigned*)&h0; o.y = *(unsigned*)&h1;
        *(uint2*)(outh + (size_t)r * E + c0) = o;
    }
}

// ------------- fp32 -> fp16 bulk convert (8 elems/thread) -------------
__global__ __launch_bounds__(256)
void f2h_kernel(const float* __restrict__ src, __half* __restrict__ dst, long long n8)
{
    long long i = (long long)blockIdx.x * blockDim.x + threadIdx.x;
    if (i >= n8) return;
    const float4* s = (const float4*)src;
    float4 a = s[2 * i], b = s[2 * i + 1];
    __half2 h0 = __float22half2_rn(make_float2(a.x, a.y));
    __half2 h1 = __float22half2_rn(make_float2(a.z, a.w));
    __half2 h2 = __float22half2_rn(make_float2(b.x, b.y));
    __half2 h3 = __float22half2_rn(make_float2(b.z, b.w));
    uint4 o;
    o.x = *(unsigned*)&h0; o.y = *(unsigned*)&h1;
    o.z = *(unsigned*)&h2; o.w = *(unsigned*)&h3;
    ((uint4*)dst)[i] = o;
}

// ------------- gather: one warp per output element -------------
__global__ __launch_bounds__(256)
void gather_kernel(const float* __restrict__ uemb, const float* __restrict__ memb,
                   const float* __restrict__ Wo, const float* __restrict__ bo,
                   const int* __restrict__ uid, const int* __restrict__ mid,
                   float* __restrict__ out, int B)
{
    int gw   = (int)((blockIdx.x * blockDim.x + threadIdx.x) >> 5);
    int lane = threadIdx.x & 31;
    if (gw >= B) return;

    const int u = uid[gw];
    const int m = mid[gw];

    float acc = 0.0f;
    {
        const float* ur = uemb + u * E;
        const float* mr = memb + m * E;
        #pragma unroll
        for (int rep = 0; rep < 2; rep++) {
            int e = lane + rep * 32;
            acc = fmaf(ur[e] * mr[e], Wo[e], acc);
        }
    }
    #pragma unroll
    for (int l = 0; l < L; l++) {
        const float* ul = g_us + l * NU * E + u * E;
        const float* ml = g_ms + l * NM * E + m * E;
        const float* w  = Wo + (l + 1) * E;
        #pragma unroll
        for (int rep = 0; rep < 2; rep++) {
            int e = lane + rep * 32;
            acc = fmaf(ul[e] * ml[e], w[e], acc);
        }
    }
    #pragma unroll
    for (int o = 16; o > 0; o >>= 1)
        acc += __shfl_down_sync(0xffffffffu, acc, o);
    if (lane == 0) out[gw] = acc + bo[0];
}

extern "C" void kernel_launch(void* const* d_in, const int* in_sizes, int n_in,
                              void* d_out, int out_size)
{
    const float* uadj = (const float*)d_in[0];
    const float* madj = (const float*)d_in[1];
    const float* uemb = (const float*)d_in[2];
    const float* memb = (const float*)d_in[3];
    const float* Wu   = (const float*)d_in[4];
    const float* bu   = (const float*)d_in[5];
    const float* Wm   = (const float*)d_in[6];
    const float* bm   = (const float*)d_in[7];
    const float* Wo   = (const float*)d_in[8];
    const float* bo   = (const float*)d_in[9];
    const int*   uid  = (const int*)d_in[10];
    const int*   mid  = (const int*)d_in[11];
    float* out = (float*)d_out;

    const int B = in_sizes[10];

    cudaFuncSetAttribute(gemm_half_kernel,
                         cudaFuncAttributeMaxDynamicSharedMemorySize, SMEM_BYTES);

    __half *uadjh, *madjh, *uh0, *mh0;
    cudaGetSymbolAddress((void**)&uadjh, g_uadjh);
    cudaGetSymbolAddress((void**)&madjh, g_madjh);
    cudaGetSymbolAddress((void**)&uh0,   g_uh0);
    cudaGetSymbolAddress((void**)&mh0,   g_mh0);

    // embedding converts first, then adjacency (also shifts which launch the
    // fixed ncu skip-count lands on -> adjacency convert / GEMM evidence)
    const long long nue8 = (long long)NU * E / 8;
    const long long nme8 = (long long)NM * E / 8;
    f2h_kernel<<<(unsigned)((nue8 + 255) / 256), 256>>>(uemb, uh0, nue8);
    f2h_kernel<<<(unsigned)((nme8 + 255) / 256), 256>>>(memb, mh0, nme8);
    const long long nadj8 = (long long)NU * NM / 8;
    f2h_kernel<<<(unsigned)((nadj8 + 255) / 256), 256>>>(uadj, uadjh, nadj8);
    f2h_kernel<<<(unsigned)((nadj8 + 255) / 256), 256>>>(madj, madjh, nadj8);

    for (int l = 0; l < L; l++) {
        gemm_half_kernel<<<GRID_G, 128, SMEM_BYTES>>>(l);
        reduce_epilogue_kernel<<<63 + 125, 128>>>(uemb, memb, Wu, bu, Wm, bm, l);
    }

    const int gblocks = (B + 7) / 8;
    gather_kernel<<<gblocks, 256>>>(uemb, memb, Wo, bo, uid, mid, out, B);
}

// round 16
// speedup vs baseline: 4.9142x; 1.0767x over previous
#include <cuda_runtime.h>
#include <cuda_fp16.h>
#include <mma.h>
#include <cstdint>

using namespace nvcuda;

constexpr int NU = 16000;
constexpr int NM = 8000;
constexpr int E  = 64;
constexpr int L  = 3;

// fp16 adjacency (written by layer-0 GEMM as a byproduct; read by layers 1-2)
__device__ __align__(16) __half g_uadjh[(size_t)NU * NM];
__device__ __align__(16) __half g_madjh[(size_t)NM * NU];
// fp16 input embeddings (layer-0 B operands)
__device__ __align__(16) __half g_uh0[NU * E];
__device__ __align__(16) __half g_mh0[NM * E];
// fp32 layer outputs (self-term of next layer + gather)
__device__ __align__(16) float g_us[L * NU * E];
__device__ __align__(16) float g_ms[L * NM * E];
// fp16 layer outputs (next layer's B operand)
__device__ __align__(16) __half g_ush[L * NU * E];
__device__ __align__(16) __half g_msh[L * NM * E];
// split-K partial accumulators
constexpr int SPLIT_M = 4;   // movie side: K=16000 -> 4 x 4000
constexpr int SPLIT_U = 2;   // user  side: K= 8000 -> 2 x 4000
__device__ __align__(16) float g_pm[SPLIT_M * NM * E];
__device__ __align__(16) float g_pu[SPLIT_U * NU * E];

// ------------------- cp.async helpers -------------------
__device__ __forceinline__ unsigned sptr(const void* p) {
    return (unsigned)__cvta_generic_to_shared(p);
}
#define CP16(dst, src) asm volatile("cp.async.cg.shared.global [%0], [%1], 16;\n" :: "r"(dst), "l"(src))
#define CP_COMMIT()    asm volatile("cp.async.commit_group;\n")
#define CP_WAIT(n)     asm volatile("cp.async.wait_group %0;\n" :: "n"(n))

// ------------------- tiling -------------------
constexpr int BK      = 32;           // k-chunk (halves / floats)
constexpr int STAGES  = 3;
constexpr int LDA_H   = 40;           // fp16 A pitch (80 B rows, 16B-aligned)
constexpr int LDB_H   = 72;           // fp16 B pitch (144 B rows) - conflict-free LDSM
constexpr int LDA32   = 36;           // fp32 A staging pitch (144 B rows)
constexpr int A_STAGE_H  = 64 * LDA_H;   // 2560 halves
constexpr int B_STAGE_H  = BK * LDB_H;   // 2304 halves
constexpr int A32_STAGE  = 64 * LDA32;   // 2304 floats
constexpr int SMEM_PLAIN = STAGES * (A_STAGE_H + B_STAGE_H) * 2;          // 29184 B
constexpr int SMEM_CONV  = STAGES * A32_STAGE * 4 + SMEM_PLAIN;           // 56832 B

constexpr int NITER   = 125;          // 4000 / BK, identical for every CTA
constexpr int GRID_G  = 125 * SPLIT_M + 250 * SPLIT_U;  // 500 + 500 = 1000

// CONV=true (layer 0): A operand streamed from fp32 adjacency, converted to
// fp16 in smem (feeding wmma) AND written back to the fp16 adjacency buffer.
template<bool CONV>
__global__ __launch_bounds__(128)
void gemm_half_kernel(int layer, const float* __restrict__ uadj32,
                      const float* __restrict__ madj32)
{
    extern __shared__ char smraw[];
    float*  A32 = (float*)smraw;                                   // CONV only
    __half* sh16 = (__half*)(smraw + (CONV ? STAGES * A32_STAGE * 4 : 0));
    __half* As = sh16;                               // [STAGES][A_STAGE_H]
    __half* Bs = sh16 + STAGES * A_STAGE_H;          // [STAGES][B_STAGE_H]

    const int bid = blockIdx.x;
    const __half *adjh, *bh;
    const float* adj32 = nullptr;
    __half* adjh_w = nullptr;
    float* part;
    int tile, K;
    size_t off;
    if (bid < 125 * SPLIT_M) {                     // movie side
        tile = bid >> 2;
        const int split = bid & 3;
        K = NU;
        off  = (size_t)tile * 64 * K + (size_t)split * 4000;
        adjh = g_madjh + off;
        if (CONV) { adj32 = madj32 + off; adjh_w = g_madjh + off; }
        bh   = ((layer == 0) ? g_uh0 : (g_ush + (layer - 1) * NU * E))
               + (size_t)(split * 4000) * E;
        part = g_pm + (size_t)split * NM * E;
    } else {                                        // user side
        const int u = bid - 125 * SPLIT_M;
        tile = u >> 1;
        const int split = u & 1;
        K = NM;
        off  = (size_t)tile * 64 * K + (size_t)split * 4000;
        adjh = g_uadjh + off;
        if (CONV) { adj32 = uadj32 + off; adjh_w = g_uadjh + off; }
        bh   = ((layer == 0) ? g_mh0 : (g_msh + (layer - 1) * NM * E))
               + (size_t)(split * 4000) * E;
        part = g_pu + (size_t)split * NU * E;
    }
    const int m0 = tile * 64;

    const int t   = threadIdx.x;
    const int wid = t >> 5;
    const int wr  = wid >> 1;                      // 2x2 warp grid over 64x64
    const int wc  = wid & 1;

    auto load_stage = [&](int st, int k0) {
        __half* b_s = Bs + st * B_STAGE_H;
        if (CONV) {
            float* a_s = A32 + st * A32_STAGE;
            #pragma unroll
            for (int rep = 0; rep < 4; rep++) {    // A: 64 rows x 32 fp32 (8 chunks/row)
                int id = t + rep * 128;
                int r = id >> 3, c = id & 7;
                CP16(sptr(a_s + r * LDA32 + c * 4), adj32 + (size_t)r * K + k0 + c * 4);
            }
        } else {
            __half* a_s = As + st * A_STAGE_H;
            #pragma unroll
            for (int rep = 0; rep < 2; rep++) {    // A: 64 rows x 32 halves (4 chunks/row)
                int id = t + rep * 128;
                int r = id >> 2, c = id & 3;
                CP16(sptr(a_s + r * LDA_H + c * 8), adjh + (size_t)r * K + k0 + c * 8);
            }
        }
        #pragma unroll
        for (int rep = 0; rep < 2; rep++) {        // B: 32 rows x 64 halves
            int id = t + rep * 128;
            int r = id >> 3, c = id & 7;
            CP16(sptr(b_s + r * LDB_H + c * 8), bh + (size_t)(k0 + r) * E + c * 8);
        }
    };

    // fp32 -> fp16: smem staging -> fp16 smem (for wmma) + gmem write-back.
    // Thread t owns row r = t>>1, half h = t&1 (16 consecutive floats).
    auto convert_stage = [&](int st, int k0) {
        const float* s = A32 + st * A32_STAGE + (t >> 1) * LDA32 + (t & 1) * 16;
        uint4 o0, o1;
        {
            __half2 h0 = __float22half2_rn(make_float2(s[0],  s[1]));
            __half2 h1 = __float22half2_rn(make_float2(s[2],  s[3]));
            __half2 h2 = __float22half2_rn(make_float2(s[4],  s[5]));
            __half2 h3 = __float22half2_rn(make_float2(s[6],  s[7]));
            o0.x = *(unsigned*)&h0; o0.y = *(unsigned*)&h1;
            o0.z = *(unsigned*)&h2; o0.w = *(unsigned*)&h3;
            __half2 h4 = __float22half2_rn(make_float2(s[8],  s[9]));
            __half2 h5 = __float22half2_rn(make_float2(s[10], s[11]));
            __half2 h6 = __float22half2_rn(make_float2(s[12], s[13]));
            __half2 h7 = __float22half2_rn(make_float2(s[14], s[15]));
            o1.x = *(unsigned*)&h4; o1.y = *(unsigned*)&h5;
            o1.z = *(unsigned*)&h6; o1.w = *(unsigned*)&h7;
        }
        uint4* d = (uint4*)(As + st * A_STAGE_H + (t >> 1) * LDA_H + (t & 1) * 16);
        d[0] = o0; d[1] = o1;
        uint4* g = (uint4*)(adjh_w + (size_t)(t >> 1) * K + k0 + (t & 1) * 16);
        g[0] = o0; g[1] = o1;
    };

    wmma::fragment<wmma::accumulator, 16, 16, 16, float> acc[2][2];
    #pragma unroll
    for (int i = 0; i < 2; i++)
        #pragma unroll
        for (int j = 0; j < 2; j++)
            wmma::fill_fragment(acc[i][j], 0.0f);

    #pragma unroll
    for (int st = 0; st < STAGES - 1; st++) { load_stage(st, st * BK); CP_COMMIT(); }

    int stc = 0, stn = STAGES - 1;                 // consume / next-fill stage slots
    for (int k = 0; k < NITER; k++) {
        CP_WAIT(STAGES - 2);                       // stage k resident
        __syncthreads();                           // everyone done reading stage k-1

        const int kn = k + STAGES - 1;
        if (kn < NITER) load_stage(stn, kn * BK);
        CP_COMMIT();
        if (++stn == STAGES) stn = 0;

        if (CONV) {
            convert_stage(stc, k * BK);
            __syncthreads();                       // fp16 tile visible to all warps
        }

        const __half* a_s = As + stc * A_STAGE_H;
        const __half* b_s = Bs + stc * B_STAGE_H;
        if (++stc == STAGES) stc = 0;

        #pragma unroll
        for (int kk = 0; kk < BK; kk += 16) {
            wmma::fragment<wmma::matrix_a, 16, 16, 16, __half, wmma::row_major> a[2];
            wmma::fragment<wmma::matrix_b, 16, 16, 16, __half, wmma::row_major> b[2];
            #pragma unroll
            for (int i = 0; i < 2; i++)
                wmma::load_matrix_sync(a[i], a_s + (wr * 32 + 16 * i) * LDA_H + kk, LDA_H);
            #pragma unroll
            for (int j = 0; j < 2; j++)
                wmma::load_matrix_sync(b[j], b_s + kk * LDB_H + wc * 32 + 16 * j, LDB_H);
            #pragma unroll
            for (int i = 0; i < 2; i++)
                #pragma unroll
                for (int j = 0; j < 2; j++)
                    wmma::mma_sync(acc[i][j], a[i], b[j], acc[i][j]);
        }
    }

    // dump 64x64 fp32 partial tile straight to gmem
    #pragma unroll
    for (int i = 0; i < 2; i++)
        #pragma unroll
        for (int j = 0; j < 2; j++)
            wmma::store_matrix_sync(part + (size_t)(m0 + wr * 32 + 16 * i) * E
                                         + (wc * 32 + 16 * j),
                                    acc[i][j], E, wmma::mem_row_major);
}

// ------------- reduce partials + fused epilogue -------------
// blocks 0..62: movie rows (63*128 >= 8000); blocks 63..187: user rows.
__global__ __launch_bounds__(128)
void reduce_epilogue_kernel(const float* __restrict__ uemb,
                            const float* __restrict__ memb,
                            const float* __restrict__ Wu,
                            const float* __restrict__ bu,
                            const float* __restrict__ Wm,
                            const float* __restrict__ bm,
                            int layer)
{
    __shared__ float Ws[64 * 65];
    const int bid = blockIdx.x;
    const int t   = threadIdx.x;

    int row0, Mtot, S;
    const float *part, *self, *W, *bias;
    float* outp; __half* outh;
    if (bid < 63) {                                   // movie
        row0 = bid * 128; Mtot = NM; S = SPLIT_M;
        part = g_pm;
        self = (layer == 0) ? memb : (g_ms + (layer - 1) * NM * E);
        W = Wm + layer * E * E; bias = bm + layer * E;
        outp = g_ms + layer * NM * E;  outh = g_msh + layer * NM * E;
    } else {                                          // user
        row0 = (bid - 63) * 128; Mtot = NU; S = SPLIT_U;
        part = g_pu;
        self = (layer == 0) ? uemb : (g_us + (layer - 1) * NU * E);
        W = Wu + layer * E * E; bias = bu + layer * E;
        outp = g_us + layer * NU * E;  outh = g_ush + layer * NU * E;
    }

    for (int s = t; s < E * E; s += 128)
        Ws[(s >> 6) * 65 + (s & 63)] = W[s];
    __syncthreads();

    const int r = row0 + t;
    if (r >= Mtot) return;

    float tv[64];
    {
        const float4* sp = (const float4*)(self + (size_t)r * E);
        #pragma unroll
        for (int i = 0; i < 16; i++) {
            float4 v = sp[i];
            tv[4 * i + 0] = v.x; tv[4 * i + 1] = v.y;
            tv[4 * i + 2] = v.z; tv[4 * i + 3] = v.w;
        }
    }
    for (int s = 0; s < S; s++) {
        const float4* pp = (const float4*)(part + (size_t)s * Mtot * E + (size_t)r * E);
        #pragma unroll
        for (int i = 0; i < 16; i++) {
            float4 v = pp[i];
            tv[4 * i + 0] += v.x; tv[4 * i + 1] += v.y;
            tv[4 * i + 2] += v.z; tv[4 * i + 3] += v.w;
        }
    }

    for (int c0 = 0; c0 < 64; c0 += 4) {
        float a0 = 2.0f * bias[c0 + 0];
        float a1 = 2.0f * bias[c0 + 1];
        float a2 = 2.0f * bias[c0 + 2];
        float a3 = 2.0f * bias[c0 + 3];
        const float* w0 = Ws + (c0 + 0) * 65;
        const float* w1 = Ws + (c0 + 1) * 65;
        const float* w2 = Ws + (c0 + 2) * 65;
        const float* w3 = Ws + (c0 + 3) * 65;
        #pragma unroll
        for (int k = 0; k < 64; k++) {
            float tk = tv[k];
            a0 = fmaf(tk, w0[k], a0);
            a1 = fmaf(tk, w1[k], a1);
            a2 = fmaf(tk, w2[k], a2);
            a3 = fmaf(tk, w3[k], a3);
        }
        a0 = (a0 >= 0.0f) ? a0 : 0.01f * a0;
        a1 = (a1 >= 0.0f) ? a1 : 0.01f * a1;
        a2 = (a2 >= 0.0f) ? a2 : 0.01f * a2;
        a3 = (a3 >= 0.0f) ? a3 : 0.01f * a3;
        *(float4*)(outp + (size_t)r * E + c0) = make_float4(a0, a1, a2, a3);
        __half2 h0 = __float22half2_rn(make_float2(a0, a1));
        __half2 h1 = __float22half2_rn(make_float2(a2, a3));
        uint2 o;
        o.x = *(unsigned*)&h0; o.y = *(unsigned*)&h1;
        *(uint2*)(outh + (size_t)r * E + c0) = o;
    }
}

// ------------- fp32 -> fp16 bulk convert (embeddings only) -------------
__global__ __launch_bounds__(256)
void f2h_kernel(const float* __restrict__ src, __half* __restrict__ dst, long long n8)
{
    long long i = (long long)blockIdx.x * blockDim.x + threadIdx.x;
    if (i >= n8) return;
    const float4* s = (const float4*)src;
    float4 a = s[2 * i], b = s[2 * i + 1];
    __half2 h0 = __float22half2_rn(make_float2(a.x, a.y));
    __half2 h1 = __float22half2_rn(make_float2(a.z, a.w));
    __half2 h2 = __float22half2_rn(make_float2(b.x, b.y));
    __half2 h3 = __float22half2_rn(make_float2(b.z, b.w));
    uint4 o;
    o.x = *(unsigned*)&h0; o.y = *(unsigned*)&h1;
    o.z = *(unsigned*)&h2; o.w = *(unsigned*)&h3;
    ((uint4*)dst)[i] = o;
}

// ------------- gather: one warp per output element -------------
__global__ __launch_bounds__(256)
void gather_kernel(const float* __restrict__ uemb, const float* __restrict__ memb,
                   const float* __restrict__ Wo, const float* __restrict__ bo,
                   const int* __restrict__ uid, const int* __restrict__ mid,
                   float* __restrict__ out, int B)
{
    int gw   = (int)((blockIdx.x * blockDim.x + threadIdx.x) >> 5);
    int lane = threadIdx.x & 31;
    if (gw >= B) return;

    const int u = uid[gw];
    const int m = mid[gw];

    float acc = 0.0f;
    {
        const float* ur = uemb + u * E;
        const float* mr = memb + m * E;
        #pragma unroll
        for (int rep = 0; rep < 2; rep++) {
            int e = lane + rep * 32;
            acc = fmaf(ur[e] * mr[e], Wo[e], acc);
        }
    }
    #pragma unroll
    for (int l = 0; l < L; l++) {
        const float* ul = g_us + l * NU * E + u * E;
        const float* ml = g_ms + l * NM * E + m * E;
        const float* w  = Wo + (l + 1) * E;
        #pragma unroll
        for (int rep = 0; rep < 2; rep++) {
            int e = lane + rep * 32;
            acc = fmaf(ul[e] * ml[e], w[e], acc);
        }
    }
    #pragma unroll
    for (int o = 16; o > 0; o >>= 1)
        acc += __shfl_down_sync(0xffffffffu, acc, o);
    if (lane == 0) out[gw] = acc + bo[0];
}

extern "C" void kernel_launch(void* const* d_in, const int* in_sizes, int n_in,
                              void* d_out, int out_size)
{
    const float* uadj = (const float*)d_in[0];
    const float* madj = (const float*)d_in[1];
    const float* uemb = (const float*)d_in[2];
    const float* memb = (const float*)d_in[3];
    const float* Wu   = (const float*)d_in[4];
    const float* bu   = (const float*)d_in[5];
    const float* Wm   = (const float*)d_in[6];
    const float* bm   = (const float*)d_in[7];
    const float* Wo   = (const float*)d_in[8];
    const float* bo   = (const float*)d_in[9];
    const int*   uid  = (const int*)d_in[10];
    const int*   mid  = (const int*)d_in[11];
    float* out = (float*)d_out;

    const int B = in_sizes[10];

    cudaFuncSetAttribute(gemm_half_kernel<true>,
                         cudaFuncAttributeMaxDynamicSharedMemorySize, SMEM_CONV);
    cudaFuncSetAttribute(gemm_half_kernel<false>,
                         cudaFuncAttributeMaxDynamicSharedMemorySize, SMEM_PLAIN);

    __half *uh0, *mh0;
    cudaGetSymbolAddress((void**)&uh0, g_uh0);
    cudaGetSymbolAddress((void**)&mh0, g_mh0);

    // only the (tiny) embedding converts remain standalone
    const long long nue8 = (long long)NU * E / 8;
    const long long nme8 = (long long)NM * E / 8;
    f2h_kernel<<<(unsigned)((nue8 + 255) / 256), 256>>>(uemb, uh0, nue8);
    f2h_kernel<<<(unsigned)((nme8 + 255) / 256), 256>>>(memb, mh0, nme8);

    // layer 0: fused fp32-adjacency convert + GEMM (writes g_*adjh)
    gemm_half_kernel<true><<<GRID_G, 128, SMEM_CONV>>>(0, uadj, madj);
    reduce_epilogue_kernel<<<63 + 125, 128>>>(uemb, memb, Wu, bu, Wm, bm, 0);

    for (int l = 1; l < L; l++) {
        gemm_half_kernel<false><<<GRID_G, 128, SMEM_PLAIN>>>(l, nullptr, nullptr);
        reduce_epilogue_kernel<<<63 + 125, 128>>>(uemb, memb, Wu, bu, Wm, bm, l);
    }

    const int gblocks = (B + 7) / 8;
    gather_kernel<<<gblocks, 256>>>(uemb, memb, Wo, bo, uid, mid, out, B);
}